// round 1
// baseline (speedup 1.0000x reference)
#include <cuda_runtime.h>
#include <cstdint>

#define L_LEVELS 12
#define T_SIZE   (1u << 19)
#define T_MASK   (T_SIZE - 1u)
#define N_POINTS 524288
#define D_OUT    257
#define FEAT     24          // L * F
#define BLOCK    128         // threads per block = points per block; also 256 columns (2/thread)

// ---------- packed f32x2 helpers (Blackwell FFMA2 path) ----------
__device__ __forceinline__ unsigned long long pack2(float lo, float hi) {
    unsigned long long r;
    asm("mov.b64 %0, {%1, %2};" : "=l"(r) : "f"(lo), "f"(hi));
    return r;
}
__device__ __forceinline__ void unpack2(unsigned long long v, float& lo, float& hi) {
    asm("mov.b64 {%0, %1}, %2;" : "=f"(lo), "=f"(hi) : "l"(v));
}
__device__ __forceinline__ unsigned long long fma2(unsigned long long a,
                                                   unsigned long long b,
                                                   unsigned long long c) {
    unsigned long long d;
    asm("fma.rn.f32x2 %0, %1, %2, %3;" : "=l"(d) : "l"(a), "l"(b), "l"(c));
    return d;
}

// Per-level grid resolutions: floor(16 * growth^l), growth = exp(ln(128)/11).
// Exactly representable in f32; matches the numpy-computed int32 values.
__device__ __constant__ float RESF[L_LEVELS] = {
    16.f, 24.f, 38.f, 60.f, 93.f, 145.f, 225.f, 350.f, 545.f, 847.f, 1317.f, 2048.f
};

__global__ __launch_bounds__(BLOCK, 4)
void hashgrid_fused_kernel(const float*  __restrict__ xin,    // [N,3]
                           const float2* __restrict__ tab,    // [12, T] of float2
                           const float*  __restrict__ W,      // [24, 257]
                           const float*  __restrict__ bias,   // [257]
                           float*        __restrict__ out)    // [N, 257]
{
    __shared__ float2 semb[BLOCK][FEAT];   // duplicated features (e,e) per point
    __shared__ float  wc256[FEAT];         // W[:,256]
    __shared__ float  b256s;

    const int tid = threadIdx.x;

    if (tid < FEAT) wc256[tid] = W[tid * D_OUT + 256];
    if (tid == FEAT) b256s = bias[256];
    __syncthreads();

    // ---------------- Phase 1: hash encode (thread = point) ----------------
    const int p = blockIdx.x * BLOCK + tid;
    const float x = xin[3 * p + 0];
    const float y = xin[3 * p + 1];
    const float z = xin[3 * p + 2];

    const unsigned P1 = 2654435761u;
    const unsigned P2 = 805459861u;

    float acc256 = b256s;

#pragma unroll
    for (int l = 0; l < L_LEVELS; l++) {
        const float resf = RESF[l];
        const float2* tl = tab + (size_t)l * T_SIZE;

        float px = x * resf, py = y * resf, pz = z * resf;
        float fx = floorf(px), fy = floorf(py), fz = floorf(pz);
        float tx = px - fx,   ty = py - fy,   tz = pz - fz;

        unsigned cx = (unsigned)fx, cy = (unsigned)fy, cz = (unsigned)fz;
        unsigned hx0 = cx,        hx1 = cx + 1u;
        unsigned hy0 = cy * P1,   hy1 = hy0 + P1;
        unsigned hz0 = cz * P2,   hz1 = hz0 + P2;

        unsigned idx[8];
        idx[0] = (hx0 ^ hy0 ^ hz0) & T_MASK;
        idx[1] = (hx0 ^ hy0 ^ hz1) & T_MASK;
        idx[2] = (hx0 ^ hy1 ^ hz0) & T_MASK;
        idx[3] = (hx0 ^ hy1 ^ hz1) & T_MASK;
        idx[4] = (hx1 ^ hy0 ^ hz0) & T_MASK;
        idx[5] = (hx1 ^ hy0 ^ hz1) & T_MASK;
        idx[6] = (hx1 ^ hy1 ^ hz0) & T_MASK;
        idx[7] = (hx1 ^ hy1 ^ hz1) & T_MASK;

        float2 f[8];
#pragma unroll
        for (int i = 0; i < 8; i++) f[i] = __ldg(tl + idx[i]);

        const float ux = 1.0f - tx, uy = 1.0f - ty, uz = 1.0f - tz;
        float wxy[4];
        wxy[0] = ux * uy;   // ox=0, oy=0
        wxy[1] = ux * ty;   // ox=0, oy=1
        wxy[2] = tx * uy;   // ox=1, oy=0
        wxy[3] = tx * ty;   // ox=1, oy=1

        float e0 = 0.0f, e1 = 0.0f;
#pragma unroll
        for (int i = 0; i < 8; i++) {
            float w = wxy[i >> 1] * ((i & 1) ? tz : uz);
            e0 = fmaf(w, f[i].x, e0);
            e1 = fmaf(w, f[i].y, e1);
        }

        semb[tid][2 * l + 0] = make_float2(e0, e0);
        semb[tid][2 * l + 1] = make_float2(e1, e1);
        acc256 = fmaf(e0, wc256[2 * l + 0], acc256);
        acc256 = fmaf(e1, wc256[2 * l + 1], acc256);
    }

    // odd 257th column, streaming store (keep tables resident in L2)
    __stcs(out + (size_t)p * D_OUT + 256, acc256);

    __syncthreads();

    // ---------------- Phase 2: GEMM head (thread owns 2 adjacent columns) ----
    const int c0 = 2 * tid;                       // columns [c0, c0+1], 0..255
    unsigned long long wreg[FEAT];
#pragma unroll
    for (int k = 0; k < FEAT; k++)
        wreg[k] = pack2(W[k * D_OUT + c0], W[k * D_OUT + c0 + 1]);
    const unsigned long long bpair = pack2(bias[c0], bias[c0 + 1]);

    float* outb = out + (size_t)blockIdx.x * BLOCK * D_OUT;
    const unsigned long long* es = (const unsigned long long*)&semb[0][0];

    for (int g = 0; g < BLOCK; g += 4) {
        unsigned long long a0 = bpair, a1 = bpair, a2 = bpair, a3 = bpair;
#pragma unroll
        for (int k = 0; k < FEAT; k++) {
            unsigned long long e0 = es[(g + 0) * FEAT + k];  // broadcast LDS.64
            unsigned long long e1 = es[(g + 1) * FEAT + k];
            unsigned long long e2 = es[(g + 2) * FEAT + k];
            unsigned long long e3 = es[(g + 3) * FEAT + k];
            a0 = fma2(e0, wreg[k], a0);
            a1 = fma2(e1, wreg[k], a1);
            a2 = fma2(e2, wreg[k], a2);
            a3 = fma2(e3, wreg[k], a3);
        }
        float lo, hi;
        unpack2(a0, lo, hi);
        __stcs(outb + (size_t)(g + 0) * D_OUT + c0, lo);
        __stcs(outb + (size_t)(g + 0) * D_OUT + c0 + 1, hi);
        unpack2(a1, lo, hi);
        __stcs(outb + (size_t)(g + 1) * D_OUT + c0, lo);
        __stcs(outb + (size_t)(g + 1) * D_OUT + c0 + 1, hi);
        unpack2(a2, lo, hi);
        __stcs(outb + (size_t)(g + 2) * D_OUT + c0, lo);
        __stcs(outb + (size_t)(g + 2) * D_OUT + c0 + 1, hi);
        unpack2(a3, lo, hi);
        __stcs(outb + (size_t)(g + 3) * D_OUT + c0, lo);
        __stcs(outb + (size_t)(g + 3) * D_OUT + c0 + 1, hi);
    }
}

extern "C" void kernel_launch(void* const* d_in, const int* in_sizes, int n_in,
                              void* d_out, int out_size) {
    const float*  xin  = (const float*) d_in[0];   // [N,3]
    const float2* tab  = (const float2*)d_in[1];   // [12,T,2] -> float2
    const float*  W    = (const float*) d_in[2];   // [24,257]
    const float*  bias = (const float*) d_in[3];   // [257]
    float* out = (float*)d_out;

    dim3 grid(N_POINTS / BLOCK);   // 4096 blocks, 128 points each
    hashgrid_fused_kernel<<<grid, BLOCK>>>(xin, tab, W, bias, out);
}

// round 2
// speedup vs baseline: 1.3027x; 1.3027x over previous
#include <cuda_runtime.h>
#include <cstdint>

#define L_LEVELS 12
#define T_SIZE   (1u << 19)
#define T_MASK   (T_SIZE - 1u)
#define N_POINTS 524288
#define D_OUT    257
#define FEAT     24          // L * F
#define BLOCK    64          // threads per block = points per block (2 warps)
#define EMB_PAD  28          // padded row stride in floats (16B aligned, 7 float4s)

// ---------- packed f32x2 helpers (Blackwell FFMA2 path) ----------
__device__ __forceinline__ unsigned long long pack2(float lo, float hi) {
    unsigned long long r;
    asm("mov.b64 %0, {%1, %2};" : "=l"(r) : "f"(lo), "f"(hi));
    return r;
}
__device__ __forceinline__ void unpack2(unsigned long long v, float& lo, float& hi) {
    asm("mov.b64 {%0, %1}, %2;" : "=f"(lo), "=f"(hi) : "l"(v));
}
__device__ __forceinline__ unsigned long long fma2(unsigned long long a,
                                                   unsigned long long b,
                                                   unsigned long long c) {
    unsigned long long d;
    asm("fma.rn.f32x2 %0, %1, %2, %3;" : "=l"(d) : "l"(a), "l"(b), "l"(c));
    return d;
}

// Per-level grid resolutions: floor(16 * growth^l), growth = exp(ln(128)/11).
__device__ __constant__ float RESF[L_LEVELS] = {
    16.f, 24.f, 38.f, 60.f, 93.f, 145.f, 225.f, 350.f, 545.f, 847.f, 1317.f, 2048.f
};

__global__ __launch_bounds__(BLOCK, 8)
void hashgrid_fused_kernel(const float*  __restrict__ xin,    // [N,3]
                           const float2* __restrict__ tab,    // [12, T] of float2
                           const float*  __restrict__ W,      // [24, 257]
                           const float*  __restrict__ bias,   // [257]
                           float*        __restrict__ out)    // [N, 257]
{
    __shared__ float semb[BLOCK][EMB_PAD];  // 24 features/row, padded to 28
    __shared__ float wc256[FEAT];           // W[:,256]
    __shared__ float b256s;

    const int tid = threadIdx.x;

    if (tid < FEAT) wc256[tid] = W[tid * D_OUT + 256];
    if (tid == FEAT) b256s = bias[256];
    __syncthreads();

    // ---------------- Phase 1: hash encode (thread = point) ----------------
    const int p = blockIdx.x * BLOCK + tid;
    const float x = xin[3 * p + 0];
    const float y = xin[3 * p + 1];
    const float z = xin[3 * p + 2];

    const unsigned P1 = 2654435761u;
    const unsigned P2 = 805459861u;

    float acc256 = b256s;

#pragma unroll
    for (int l = 0; l < L_LEVELS; l++) {
        const float resf = RESF[l];
        const float2* tl = tab + (size_t)l * T_SIZE;

        float px = x * resf, py = y * resf, pz = z * resf;
        float fx = floorf(px), fy = floorf(py), fz = floorf(pz);
        float tx = px - fx,   ty = py - fy,   tz = pz - fz;

        unsigned cx = (unsigned)fx, cy = (unsigned)fy, cz = (unsigned)fz;
        unsigned hx0 = cx,        hx1 = cx + 1u;
        unsigned hy0 = cy * P1,   hy1 = hy0 + P1;
        unsigned hz0 = cz * P2,   hz1 = hz0 + P2;

        unsigned idx[8];
        idx[0] = (hx0 ^ hy0 ^ hz0) & T_MASK;
        idx[1] = (hx0 ^ hy0 ^ hz1) & T_MASK;
        idx[2] = (hx0 ^ hy1 ^ hz0) & T_MASK;
        idx[3] = (hx0 ^ hy1 ^ hz1) & T_MASK;
        idx[4] = (hx1 ^ hy0 ^ hz0) & T_MASK;
        idx[5] = (hx1 ^ hy0 ^ hz1) & T_MASK;
        idx[6] = (hx1 ^ hy1 ^ hz0) & T_MASK;
        idx[7] = (hx1 ^ hy1 ^ hz1) & T_MASK;

        float2 f[8];
#pragma unroll
        for (int i = 0; i < 8; i++) f[i] = __ldg(tl + idx[i]);

        const float ux = 1.0f - tx, uy = 1.0f - ty, uz = 1.0f - tz;
        float wxy[4];
        wxy[0] = ux * uy;
        wxy[1] = ux * ty;
        wxy[2] = tx * uy;
        wxy[3] = tx * ty;

        float e0 = 0.0f, e1 = 0.0f;
#pragma unroll
        for (int i = 0; i < 8; i++) {
            float w = wxy[i >> 1] * ((i & 1) ? tz : uz);
            e0 = fmaf(w, f[i].x, e0);
            e1 = fmaf(w, f[i].y, e1);
        }

        // non-duplicated features, 8B store per level
        *reinterpret_cast<float2*>(&semb[tid][2 * l]) = make_float2(e0, e1);
        acc256 = fmaf(e0, wc256[2 * l + 0], acc256);
        acc256 = fmaf(e1, wc256[2 * l + 1], acc256);
    }

    // odd 257th column, streaming store
    __stcs(out + (size_t)p * D_OUT + 256, acc256);

    __syncthreads();

    // ------- Phase 2: GEMM head. Thread owns 4 strided columns {t, t+64, t+128, t+192}.
    // Accumulate packed over k: a = (e_{2k}, e_{2k+1}) * (W[2k][c], W[2k+1][c]); horizontal add at end.
    unsigned long long wreg[L_LEVELS][4];   // 12 k-pairs x 4 columns (96 regs)
#pragma unroll
    for (int kk = 0; kk < L_LEVELS; kk++) {
#pragma unroll
        for (int c = 0; c < 4; c++) {
            int col = tid + 64 * c;
            wreg[kk][c] = pack2(W[(2 * kk) * D_OUT + col], W[(2 * kk + 1) * D_OUT + col]);
        }
    }
    float breg[4];
#pragma unroll
    for (int c = 0; c < 4; c++) breg[c] = bias[tid + 64 * c];

    float* outb = out + (size_t)blockIdx.x * BLOCK * D_OUT;

#pragma unroll 2
    for (int r = 0; r < BLOCK; r++) {
        const float4* erow = reinterpret_cast<const float4*>(&semb[r][0]);
        unsigned long long a0 = 0, a1 = 0, a2 = 0, a3 = 0;
#pragma unroll
        for (int q = 0; q < 6; q++) {
            float4 e4 = erow[q];                 // broadcast LDS.128: 4 features
            unsigned long long p0 = pack2(e4.x, e4.y);   // (e_{4q},   e_{4q+1})
            unsigned long long p1 = pack2(e4.z, e4.w);   // (e_{4q+2}, e_{4q+3})
            a0 = fma2(p0, wreg[2 * q][0], a0);  a0 = fma2(p1, wreg[2 * q + 1][0], a0);
            a1 = fma2(p0, wreg[2 * q][1], a1);  a1 = fma2(p1, wreg[2 * q + 1][1], a1);
            a2 = fma2(p0, wreg[2 * q][2], a2);  a2 = fma2(p1, wreg[2 * q + 1][2], a2);
            a3 = fma2(p0, wreg[2 * q][3], a3);  a3 = fma2(p1, wreg[2 * q + 1][3], a3);
        }
        float lo, hi;
        float* orow = outb + (size_t)r * D_OUT;
        unpack2(a0, lo, hi); __stcs(orow + tid,       lo + hi + breg[0]);
        unpack2(a1, lo, hi); __stcs(orow + tid +  64, lo + hi + breg[1]);
        unpack2(a2, lo, hi); __stcs(orow + tid + 128, lo + hi + breg[2]);
        unpack2(a3, lo, hi); __stcs(orow + tid + 192, lo + hi + breg[3]);
    }
}

extern "C" void kernel_launch(void* const* d_in, const int* in_sizes, int n_in,
                              void* d_out, int out_size) {
    const float*  xin  = (const float*) d_in[0];   // [N,3]
    const float2* tab  = (const float2*)d_in[1];   // [12,T,2] -> float2
    const float*  W    = (const float*) d_in[2];   // [24,257]
    const float*  bias = (const float*) d_in[3];   // [257]
    float* out = (float*)d_out;

    dim3 grid(N_POINTS / BLOCK);   // 8192 blocks, 64 points each
    hashgrid_fused_kernel<<<grid, BLOCK>>>(xin, tab, W, bias, out);
}